// round 6
// baseline (speedup 1.0000x reference)
#include <cuda_runtime.h>
#include <math.h>

// Problem constants
#define BB 64      // batch B
#define TT 256     // T
#define EE 64      // E (layer0 feature dim)
#define RR 4       // rel_dim
#define NSTACK 8   // n_stack
#define NEG_INF (-1e30f)

// -------- scratch (__device__ globals; no allocations) --------
__device__ float        g_partial[128 * BB * BB];  // split-K gram partials (2MB)
__device__ float        g_adj[BB * BB];            // sparsemax(adj) row-major
__device__ unsigned int g_gkey[BB * BB];           // merged window groups per row
__device__ float        g_gcnt[BB * BB];
__device__ int          g_ng[BB];
__device__ float        g_x1[BB * TT * RR];        // layer0 output

// =====================================================================
// Layer-0 gram partial: one block per 128-wide K chunk; computes full
// 64x64 partial gram of X (row-major, row stride = K) from an smem tile.
// =====================================================================
template<int K>
__global__ void gram_partial_kernel(const float* __restrict__ Xin) {
    __shared__ float Xs[BB][129];   // pad to 129 to break bank conflicts
    const int blk = blockIdx.x;
    const int k0  = blk * 128;
    const int tid = threadIdx.x;    // 256 threads

    for (int i = tid; i < BB * 128; i += 256) {
        int r = i >> 7, c = i & 127;
        Xs[r][c] = Xin[r * K + k0 + c];
    }
    __syncthreads();

    const int tx = tid & 15, ty = tid >> 4;  // 16x16 threads, 4x4 micro-tile
    float acc[4][4];
#pragma unroll
    for (int i = 0; i < 4; ++i)
#pragma unroll
        for (int j = 0; j < 4; ++j) acc[i][j] = 0.f;

#pragma unroll 4
    for (int kk = 0; kk < 128; ++kk) {
        float a[4], b[4];
#pragma unroll
        for (int i = 0; i < 4; ++i) a[i] = Xs[ty * 4 + i][kk];
#pragma unroll
        for (int j = 0; j < 4; ++j) b[j] = Xs[tx * 4 + j][kk];
#pragma unroll
        for (int i = 0; i < 4; ++i)
#pragma unroll
            for (int j = 0; j < 4; ++j) acc[i][j] = fmaf(a[i], b[j], acc[i][j]);
    }

    float* dst = g_partial + blk * (BB * BB);
#pragma unroll
    for (int i = 0; i < 4; ++i)
#pragma unroll
        for (int j = 0; j < 4; ++j)
            dst[(ty * 4 + i) * BB + (tx * 4 + j)] = acc[i][j];
}

// =====================================================================
// Sparsemax epilogue (block-wide; work guarded to tid<64).
// Requires z[] filled and all threads synced on entry.
// Exact replica of reference semantics incl. tie handling, then builds
// merged pooling-window groups (SAME pool=4 over neighbor axis).
// =====================================================================
__device__ __forceinline__ void sparsemax_epilogue(
    int row, int tid,
    float* z, float* zs, float* cum, float* av, float* cntb,
    unsigned int* keys, int* lead, float* tau_s)
{
    float zi = 0.f;
    if (tid < BB) {
        zi = z[tid];
        int r = 0;
        for (int j = 0; j < BB; ++j) {
            float zj = z[j];
            r += (zj > zi) || (zj == zi && j < tid);
        }
        zs[r] = zi;
    }
    __syncthreads();

    if (tid == 0) {
        float c = 0.f; int ksel = 0;
        for (int j = 0; j < BB; ++j) {
            c += zs[j];
            cum[j] = c;
            if (1.0f + (float)(j + 1) * zs[j] > c) ksel++;
        }
        *tau_s = (cum[ksel - 1] - 1.0f) / (float)ksel;
    }
    __syncthreads();

    if (tid < BB) {
        const float a = fmaxf(zi - *tau_s, 0.0f);
        av[tid] = a;
        g_adj[row * BB + tid] = a;
    }
    __syncthreads();

    if (tid < BB) {
        const int lo = (tid - 1 > 0) ? tid - 1 : 0;
        const int hi = (tid + 2 < BB - 1) ? tid + 2 : BB - 1;
        int nm = 0;
        unsigned int key = 0u;
        for (int bp = lo; bp <= hi; ++bp)
            if (av[bp] > 0.0f) { key |= ((unsigned)bp) << (6 * nm); nm++; }
        const int wsz = hi - lo + 1;
        if (nm == 0) key = 0xFFFFFFFFu;             // empty window -> 0 contribution
        else key |= ((unsigned)nm << 24) | ((nm < wsz ? 1u : 0u) << 28);
        keys[tid] = key;
    }
    __syncthreads();

    if (tid < BB) {
        const unsigned int key = keys[tid];
        int cnt = 0, leader = (key != 0xFFFFFFFFu);
        if (leader) {
            for (int j = 0; j < BB; ++j) {
                cnt += (keys[j] == key);
                if (keys[j] == key && j < tid) leader = 0;
            }
        }
        cntb[tid] = (float)cnt;
        lead[tid] = leader;
    }
    __syncthreads();

    if (tid == 0) {
        int ng = 0;
        for (int j = 0; j < BB; ++j) {
            if (lead[j]) {
                g_gkey[row * BB + ng] = keys[j];
                g_gcnt[row * BB + ng] = cntb[j];
                ng++;
            }
        }
        g_ng[row] = ng;
    }
}

// =====================================================================
// Layer-0: reduce 128 split-K partials (512 threads, coalesced, 8-way
// parallel per column) then sparsemax. One block per row.
// =====================================================================
template<int NSPLIT>
__global__ void finish_sparsemax0_kernel() {
    const int row = blockIdx.x;
    const int tid = threadIdx.x;   // 512
    constexpr int PS = 512 / BB;   // 8 sub-reducers per column

    __shared__ float z[BB], zs[BB], cum[BB], av[BB], cntb[BB];
    __shared__ unsigned int keys[BB];
    __shared__ int lead[BB];
    __shared__ float tau_s;
    __shared__ float red[PS][BB];

    const int c = tid & (BB - 1), sub = tid >> 6;
    float s = 0.f;
    for (int p = sub; p < NSPLIT; p += PS)
        s += g_partial[p * (BB * BB) + row * BB + c];
    red[sub][c] = s;
    __syncthreads();

    if (tid < BB) {
        float t = 0.f;
#pragma unroll
        for (int q = 0; q < PS; ++q) t += red[q][tid];
        z[tid] = t * (1.0f / (float)TT);
    }
    __syncthreads();

    sparsemax_epilogue(row, tid, z, zs, cum, av, cntb, keys, lead, &tau_s);
}

// =====================================================================
// Layer-1: FUSED gram + sparsemax. One block per row (grid=64, 256 thr).
// x1[row] (4KB) cached in smem; streams all of g_x1 (L2-resident 256KB)
// with float4; 4 K-quarter partial sums per column reduced via smem.
// =====================================================================
__global__ void gram1_sparsemax_kernel() {
    const int row = blockIdx.x;
    const int tid = threadIdx.x;   // 256

    __shared__ float4 xrow4[TT * RR / 4];   // 1024 floats
    __shared__ float z[BB], zs[BB], cum[BB], av[BB], cntb[BB];
    __shared__ unsigned int keys[BB];
    __shared__ int lead[BB];
    __shared__ float tau_s;
    __shared__ float red[4][BB];

    const float4* x14 = (const float4*)g_x1;
    xrow4[tid] = x14[row * 256 + tid];
    __syncthreads();

    const int j = tid >> 2, q = tid & 3;    // 4 threads per column j
    float s = 0.f;
    const float4* xj = x14 + j * 256 + q * 64;
    const float4* xr = xrow4 + q * 64;
#pragma unroll 8
    for (int i = 0; i < 64; ++i) {
        float4 a = xr[i], b = xj[i];
        s += a.x * b.x + a.y * b.y + a.z * b.z + a.w * b.w;
    }
    red[q][j] = s;
    __syncthreads();

    if (tid < BB)
        z[tid] = (red[0][tid] + red[1][tid] + red[2][tid] + red[3][tid]) * (1.0f / (float)TT);
    __syncthreads();

    sparsemax_epilogue(row, tid, z, zs, cum, av, cntb, keys, lead, &tau_s);
}

// =====================================================================
// Layer-0 pooling + GEMM(W0, 64 -> 4) + relu, writes g_x1.
// Block: 256 threads = 8 warps; warp handles 4 t's; lane handles e=lane
// and e=lane+32.
// =====================================================================
__global__ void pool0_kernel(const float* __restrict__ x, const float* __restrict__ W0) {
    const int Brow = blockIdx.x;
    const int t0   = blockIdx.y * 32;
    const int tid  = threadIdx.x;
    const int lane = tid & 31, w = tid >> 5;

    __shared__ float a_s[BB];
    __shared__ unsigned int key_s[BB];
    __shared__ float cnt_s[BB];
    __shared__ float W_s[EE * RR];
    __shared__ int ng_s;

    if (tid < BB) {
        a_s[tid]   = g_adj[Brow * BB + tid];
        key_s[tid] = g_gkey[Brow * BB + tid];
        cnt_s[tid] = g_gcnt[Brow * BB + tid];
    }
    if (tid < EE * RR) W_s[tid] = W0[tid];
    if (tid == 0) ng_s = g_ng[Brow];
    __syncthreads();

    const int ng    = ng_s;
    const int tbase = t0 + w * 4;

    float acc0[4], acc1[4];
#pragma unroll
    for (int i = 0; i < 4; ++i) { acc0[i] = 0.f; acc1[i] = 0.f; }

    for (int g = 0; g < ng; ++g) {
        const unsigned int key = key_s[g];
        const float cnt = cnt_s[g];
        const int nm = (key >> 24) & 7;
        unsigned int mm = key;
        float m0[4], m1[4];
#pragma unroll
        for (int i = 0; i < 4; ++i) { m0[i] = NEG_INF; m1[i] = NEG_INF; }
        for (int u = 0; u < nm; ++u) {
            const int bp = mm & 63; mm >>= 6;
            const float avv = a_s[bp];
            const float* xp = x + bp * (TT * EE) + tbase * EE + lane;
#pragma unroll
            for (int i = 0; i < 4; ++i) {
                m0[i] = fmaxf(m0[i], avv * xp[i * EE]);
                m1[i] = fmaxf(m1[i], avv * xp[i * EE + 32]);
            }
        }
        const float zf = (key >> 28) ? 0.f : NEG_INF;
#pragma unroll
        for (int i = 0; i < 4; ++i) {
            acc0[i] += cnt * fmaxf(m0[i], zf);
            acc1[i] += cnt * fmaxf(m1[i], zf);
        }
    }

    // out[Brow, t, r] = relu(sum_e agg_e * W0[e][r]) via warp butterfly
#pragma unroll
    for (int i = 0; i < 4; ++i) {
        float res = 0.f;
#pragma unroll
        for (int rout = 0; rout < RR; ++rout) {
            float p = acc0[i] * W_s[lane * RR + rout] + acc1[i] * W_s[(lane + 32) * RR + rout];
            p += __shfl_xor_sync(0xFFFFFFFFu, p, 1);
            p += __shfl_xor_sync(0xFFFFFFFFu, p, 2);
            p += __shfl_xor_sync(0xFFFFFFFFu, p, 4);
            p += __shfl_xor_sync(0xFFFFFFFFu, p, 8);
            p += __shfl_xor_sync(0xFFFFFFFFu, p, 16);
            if (lane == rout) res = p;
        }
        if (lane < RR) g_x1[(Brow * TT + tbase + i) * RR + lane] = fmaxf(res, 0.f);
    }
}

// =====================================================================
// FUSED layer-1 pooling + GEMM(W1, 4->4) + relu + mean over T + @Wp
// + softmax. One block per B row (grid=64, 256 threads).
// Thread: r = tid&3, tl = tid>>2; covers t in {tl, tl+64, tl+128, tl+192}.
// =====================================================================
__global__ void pool1_final_kernel(const float* __restrict__ W1,
                                   const float* __restrict__ Wp,
                                   float* __restrict__ outp) {
    const int Brow = blockIdx.x;
    const int tid  = threadIdx.x;  // 256
    const int r    = tid & 3;
    const int tl   = tid >> 2;     // 0..63

    __shared__ float a_s[BB];
    __shared__ unsigned int key_s[BB];
    __shared__ float cnt_s[BB];
    __shared__ float W_s[RR * RR];
    __shared__ int ng_s;
    __shared__ float sm[8][4];

    if (tid < BB) {
        a_s[tid]   = g_adj[Brow * BB + tid];
        key_s[tid] = g_gkey[Brow * BB + tid];
        cnt_s[tid] = g_gcnt[Brow * BB + tid];
    }
    if (tid < RR * RR) W_s[tid] = W1[tid];
    if (tid == 0) ng_s = g_ng[Brow];
    __syncthreads();

    const int ng = ng_s;
    float msum = 0.f;

#pragma unroll
    for (int it = 0; it < 4; ++it) {
        const int t   = tl + it * 64;
        const int off = t * RR + r;
        float acc = 0.f;
        for (int g = 0; g < ng; ++g) {
            const unsigned int key = key_s[g];
            const int nm = (key >> 24) & 7;
            unsigned int mm = key;
            float m = NEG_INF;
            for (int u = 0; u < nm; ++u) {
                const int bp = mm & 63; mm >>= 6;
                m = fmaxf(m, a_s[bp] * g_x1[bp * (TT * RR) + off]);
            }
            if (key >> 28) m = fmaxf(m, 0.f);
            acc += cnt_s[g] * m;
        }
        // 4->4 matmul across the 4-lane r group
        float res = 0.f;
#pragma unroll
        for (int rout = 0; rout < RR; ++rout) {
            float p = acc * W_s[r * RR + rout];
            p += __shfl_xor_sync(0xFFFFFFFFu, p, 1);
            p += __shfl_xor_sync(0xFFFFFFFFu, p, 2);
            if (r == rout) res = p;
        }
        msum += fmaxf(res, 0.f);   // relu, accumulate for mean
    }

    // reduce msum over the 8 t-slots per warp (r preserved)
    msum += __shfl_xor_sync(0xFFFFFFFFu, msum, 4);
    msum += __shfl_xor_sync(0xFFFFFFFFu, msum, 8);
    msum += __shfl_xor_sync(0xFFFFFFFFu, msum, 16);

    if ((tid & 31) < 4) sm[tid >> 5][r] = msum;
    __syncthreads();
    if (tid < 4) {
        float p = 0.f;
#pragma unroll
        for (int wg = 0; wg < 8; ++wg) p += sm[wg][tid];
        sm[0][tid] = p * (1.0f / (float)TT);
    }
    __syncthreads();
    if (tid == 0) {
        float logit[NSTACK];
        float mx = NEG_INF;
#pragma unroll
        for (int n = 0; n < NSTACK; ++n) {
            float p = 0.f;
#pragma unroll
            for (int rr = 0; rr < RR; ++rr) p += sm[0][rr] * Wp[rr * NSTACK + n];
            logit[n] = p;
            mx = fmaxf(mx, p);
        }
        float se = 0.f;
#pragma unroll
        for (int n = 0; n < NSTACK; ++n) { logit[n] = expf(logit[n] - mx); se += logit[n]; }
        const float inv = 1.0f / se;
#pragma unroll
        for (int n = 0; n < NSTACK; ++n) outp[Brow * NSTACK + n] = logit[n] * inv;
    }
}

// =====================================================================
extern "C" void kernel_launch(void* const* d_in, const int* in_sizes, int n_in,
                              void* d_out, int out_size) {
    const float* x  = (const float*)d_in[0];  // [64,256,64]
    const float* W0 = (const float*)d_in[1];  // [64,4]
    const float* W1 = (const float*)d_in[2];  // [4,4]
    const float* Wp = (const float*)d_in[3];  // [4,8]
    float* out = (float*)d_out;               // [64,8]

    // ---- layer 0 ----
    gram_partial_kernel<TT * EE><<<128, 256>>>(x);
    finish_sparsemax0_kernel<128><<<BB, 512>>>();
    pool0_kernel<<<dim3(BB, TT / 32), 256>>>(x, W0);

    // ---- layer 1 (fused gram+sparsemax) ----
    gram1_sparsemax_kernel<<<BB, 256>>>();

    // ---- layer 1 pooling + tail (fused) ----
    pool1_final_kernel<<<BB, 256>>>(W1, Wp, out);
}

// round 7
// speedup vs baseline: 1.6265x; 1.6265x over previous
#include <cuda_runtime.h>
#include <math.h>

// Problem constants
#define BB 64      // batch B
#define TT 256     // T
#define EE 64      // E (layer0 feature dim)
#define RR 4       // rel_dim
#define NSTACK 8   // n_stack
#define NEG_INF (-1e30f)

// -------- scratch (__device__ globals; no allocations) --------
__device__ float g_partial[128 * BB * BB];  // split-K gram partials (2MB)
__device__ float g_x1[BB * TT * RR];        // layer0 output

// =====================================================================
// Layer-0 gram partial: one block per 128-wide K chunk; computes full
// 64x64 partial gram of X (row-major, row stride 16384).
// =====================================================================
__global__ void gram_partial_kernel(const float* __restrict__ Xin) {
    __shared__ float Xs[BB][129];   // pad to break bank conflicts
    const int blk = blockIdx.x;
    const int k0  = blk * 128;
    const int tid = threadIdx.x;    // 256 threads

    for (int i = tid; i < BB * 128; i += 256) {
        int r = i >> 7, c = i & 127;
        Xs[r][c] = Xin[r * (TT * EE) + k0 + c];
    }
    __syncthreads();

    const int tx = tid & 15, ty = tid >> 4;  // 16x16 threads, 4x4 micro-tile
    float acc[4][4];
#pragma unroll
    for (int i = 0; i < 4; ++i)
#pragma unroll
        for (int j = 0; j < 4; ++j) acc[i][j] = 0.f;

#pragma unroll 4
    for (int kk = 0; kk < 128; ++kk) {
        float a[4], b[4];
#pragma unroll
        for (int i = 0; i < 4; ++i) a[i] = Xs[ty * 4 + i][kk];
#pragma unroll
        for (int j = 0; j < 4; ++j) b[j] = Xs[tx * 4 + j][kk];
#pragma unroll
        for (int i = 0; i < 4; ++i)
#pragma unroll
            for (int j = 0; j < 4; ++j) acc[i][j] = fmaf(a[i], b[j], acc[i][j]);
    }

    float* dst = g_partial + blk * (BB * BB);
#pragma unroll
    for (int i = 0; i < 4; ++i)
#pragma unroll
        for (int j = 0; j < 4; ++j)
            dst[(ty * 4 + i) * BB + (tx * 4 + j)] = acc[i][j];
}

// =====================================================================
// Shared-memory sparsemax + pooling-group state, computed per block.
// =====================================================================
struct Epi {
    float        z[BB];
    float        zs[BB];
    float        cum[BB];
    float        av[BB];
    unsigned int keys[BB];
    unsigned int gkey[BB];
    float        gcnt[BB];
    float        wtot[2];
    unsigned int bal[2];
    int          ng;
    float        tau;
};

// Fully parallel sparsemax (exact reference semantics) + merged
// pooling-window groups (SAME pool=4 over neighbor axis).
// Entry: S->z filled, block synced. Exit: synced; av/gkey/gcnt/ng valid.
// All threads of the block must call (internal __syncthreads).
__device__ __forceinline__ void sparsemax_groups(Epi* S, int tid) {
    // rank (descending, index tiebreak) -> scatter into sorted zs
    float zi = 0.f;
    if (tid < BB) {
        zi = S->z[tid];
        int r = 0;
#pragma unroll
        for (int j = 0; j < BB; ++j) {
            float zj = S->z[j];
            r += (zj > zi) || (zj == zi && j < tid);
        }
        S->zs[r] = zi;
    }
    __syncthreads();

    // inclusive cumsum over 64 sorted values: 2-warp shfl scan
    float v = 0.f, c = 0.f;
    if (tid < BB) {
        v = S->zs[tid];
        c = v;
        const int lane = tid & 31;
#pragma unroll
        for (int d = 1; d < 32; d <<= 1) {
            float n = __shfl_up_sync(0xFFFFFFFFu, c, d);
            if (lane >= d) c += n;
        }
        if (lane == 31) S->wtot[tid >> 5] = c;
    }
    __syncthreads();
    if (tid < BB) {
        if (tid >= 32) c += S->wtot[0];
        S->cum[tid] = c;
        const int sup = (1.0f + (float)(tid + 1) * v > c) ? 1 : 0;
        unsigned b = __ballot_sync(0xFFFFFFFFu, sup);
        if ((tid & 31) == 0) S->bal[tid >> 5] = b;
    }
    __syncthreads();
    if (tid == 0) {
        const int ksel = __popc(S->bal[0]) + __popc(S->bal[1]);
        S->tau = (S->cum[ksel - 1] - 1.0f) / (float)ksel;
    }
    __syncthreads();
    if (tid < BB) S->av[tid] = fmaxf(zi - S->tau, 0.0f);
    __syncthreads();

    // per-window support-member key (window [b-1,b+2] clipped)
    unsigned int key = 0u;
    if (tid < BB) {
        const int lo = (tid - 1 > 0) ? tid - 1 : 0;
        const int hi = (tid + 2 < BB - 1) ? tid + 2 : BB - 1;
        int nm = 0;
        for (int bp = lo; bp <= hi; ++bp)
            if (S->av[bp] > 0.0f) { key |= ((unsigned)bp) << (6 * nm); nm++; }
        const int wsz = hi - lo + 1;
        if (nm == 0) key = 0xFFFFFFFFu;             // empty window -> contributes 0
        else key |= ((unsigned)nm << 24) | ((nm < wsz ? 1u : 0u) << 28);
        S->keys[tid] = key;
    }
    __syncthreads();

    // count duplicates, elect leaders, compact via ballot prefix-sum
    int cnt = 0, leader = 0;
    if (tid < BB) {
        leader = (key != 0xFFFFFFFFu);
        if (leader) {
#pragma unroll
            for (int j = 0; j < BB; ++j) {
                const unsigned kj = S->keys[j];
                cnt += (kj == key);
                if (kj == key && j < tid) leader = 0;
            }
        }
        unsigned lb = __ballot_sync(0xFFFFFFFFu, leader);
        if ((tid & 31) == 0) S->bal[tid >> 5] = lb;
    }
    __syncthreads();
    if (tid < BB && leader) {
        const unsigned lb_own = S->bal[tid >> 5];
        int pos = __popc(lb_own & ((1u << (tid & 31)) - 1u));
        if (tid >= 32) pos += __popc(S->bal[0]);
        S->gkey[pos] = key;
        S->gcnt[pos] = (float)cnt;
    }
    if (tid == 0) S->ng = __popc(S->bal[0]) + __popc(S->bal[1]);
    __syncthreads();
}

// =====================================================================
// FUSED layer-0 tail: split-K reduce -> sparsemax -> pool0 + GEMM(W0)
// + relu -> g_x1. One block per B row (grid=64, 512 threads).
// =====================================================================
__global__ __launch_bounds__(512) void fused0_kernel(const float* __restrict__ x,
                                                     const float* __restrict__ W0) {
    const int row = blockIdx.x;
    const int tid = threadIdx.x;
    __shared__ Epi S;
    __shared__ float red[8][BB];
    __shared__ float W_s[EE * RR];

    {   // split-K reduce: 8 sub-reducers per column, coalesced
        const int c = tid & 63, sub = tid >> 6;
        float s = 0.f;
#pragma unroll
        for (int p = sub; p < 128; p += 8)
            s += g_partial[p * (BB * BB) + row * BB + c];
        red[sub][c] = s;
    }
    if (tid < EE * RR) W_s[tid] = W0[tid];
    __syncthreads();
    if (tid < BB) {
        float t = 0.f;
#pragma unroll
        for (int q = 0; q < 8; ++q) t += red[q][tid];
        S.z[tid] = t * (1.0f / (float)TT);
    }
    __syncthreads();

    sparsemax_groups(&S, tid);

    // pool0: 16 warps, warp w covers t in [w*16, w*16+16), 4 t's at a time
    const int lane = tid & 31, w = tid >> 5;
    const int ng = S.ng;
#pragma unroll
    for (int ib = 0; ib < 4; ++ib) {
        const int tbase = w * 16 + ib * 4;
        float acc0[4], acc1[4];
#pragma unroll
        for (int i = 0; i < 4; ++i) { acc0[i] = 0.f; acc1[i] = 0.f; }

        for (int g = 0; g < ng; ++g) {
            const unsigned int key = S.gkey[g];
            const float cnt = S.gcnt[g];
            const int nm = (key >> 24) & 7;
            unsigned int mm = key;
            float m0[4], m1[4];
#pragma unroll
            for (int i = 0; i < 4; ++i) { m0[i] = NEG_INF; m1[i] = NEG_INF; }
            for (int u = 0; u < nm; ++u) {
                const int bp = mm & 63; mm >>= 6;
                const float avv = S.av[bp];
                const float* xp = x + bp * (TT * EE) + tbase * EE + lane;
#pragma unroll
                for (int i = 0; i < 4; ++i) {
                    m0[i] = fmaxf(m0[i], avv * xp[i * EE]);
                    m1[i] = fmaxf(m1[i], avv * xp[i * EE + 32]);
                }
            }
            const float zf = (key >> 28) ? 0.f : NEG_INF;
#pragma unroll
            for (int i = 0; i < 4; ++i) {
                acc0[i] += cnt * fmaxf(m0[i], zf);
                acc1[i] += cnt * fmaxf(m1[i], zf);
            }
        }

        // out[row, t, r] = relu(sum_e agg_e * W0[e][r]) via warp butterfly
#pragma unroll
        for (int i = 0; i < 4; ++i) {
            float res = 0.f;
#pragma unroll
            for (int rout = 0; rout < RR; ++rout) {
                float p = acc0[i] * W_s[lane * RR + rout] + acc1[i] * W_s[(lane + 32) * RR + rout];
                p += __shfl_xor_sync(0xFFFFFFFFu, p, 1);
                p += __shfl_xor_sync(0xFFFFFFFFu, p, 2);
                p += __shfl_xor_sync(0xFFFFFFFFu, p, 4);
                p += __shfl_xor_sync(0xFFFFFFFFu, p, 8);
                p += __shfl_xor_sync(0xFFFFFFFFu, p, 16);
                if (lane == rout) res = p;
            }
            if (lane < RR) g_x1[(row * TT + tbase + i) * RR + lane] = fmaxf(res, 0.f);
        }
    }
}

// =====================================================================
// FUSED layer-1: gram row (high-MLP stream of g_x1) -> sparsemax ->
// pool1 + GEMM(W1) + relu + mean over T + @Wp + softmax -> out[row].
// One block per B row (grid=64, 512 threads).
// =====================================================================
__global__ __launch_bounds__(512) void fused1_kernel(const float* __restrict__ W1,
                                                     const float* __restrict__ Wp,
                                                     float* __restrict__ outp) {
    const int row = blockIdx.x;
    const int tid = threadIdx.x;
    __shared__ Epi S;
    __shared__ float4 xrow4[TT * RR / 4];   // 1024 floats
    __shared__ float red[8][BB];
    __shared__ float W_s[RR * RR];
    __shared__ float msm[16][4];

    const float4* x14 = (const float4*)g_x1;
    if (tid < 256) xrow4[tid] = x14[row * 256 + tid];
    if (tid < RR * RR) W_s[tid] = W1[tid];
    __syncthreads();

    {   // gram row: 8 subs per column, 32 float4 each, 4 accumulators
        const int col = tid >> 3, sub = tid & 7;
        const float4* base = x14 + col * 256;
        float s0 = 0.f, s1 = 0.f, s2 = 0.f, s3 = 0.f;
#pragma unroll
        for (int i = 0; i < 32; i += 4) {
            const float4 b0 = base[(i + 0) * 8 + sub];
            const float4 b1 = base[(i + 1) * 8 + sub];
            const float4 b2 = base[(i + 2) * 8 + sub];
            const float4 b3 = base[(i + 3) * 8 + sub];
            const float4 a0 = xrow4[(i + 0) * 8 + sub];
            const float4 a1 = xrow4[(i + 1) * 8 + sub];
            const float4 a2 = xrow4[(i + 2) * 8 + sub];
            const float4 a3 = xrow4[(i + 3) * 8 + sub];
            s0 += a0.x * b0.x + a0.y * b0.y + a0.z * b0.z + a0.w * b0.w;
            s1 += a1.x * b1.x + a1.y * b1.y + a1.z * b1.z + a1.w * b1.w;
            s2 += a2.x * b2.x + a2.y * b2.y + a2.z * b2.z + a2.w * b2.w;
            s3 += a3.x * b3.x + a3.y * b3.y + a3.z * b3.z + a3.w * b3.w;
        }
        red[sub][col] = (s0 + s1) + (s2 + s3);
    }
    __syncthreads();
    if (tid < BB) {
        float t = 0.f;
#pragma unroll
        for (int q = 0; q < 8; ++q) t += red[q][tid];
        S.z[tid] = t * (1.0f / (float)TT);
    }
    __syncthreads();

    sparsemax_groups(&S, tid);

    // pool1 + W1 + relu + mean accumulate
    const int r  = tid & 3;
    const int tq = tid >> 2;   // 0..127 -> t in {tq, tq+128}
    const int ng = S.ng;
    const float* x1f = (const float*)g_x1;
    float msum = 0.f;
#pragma unroll
    for (int half = 0; half < 2; ++half) {
        const int t = tq + half * 128;
        float acc = 0.f;
        for (int g = 0; g < ng; ++g) {
            const unsigned int key = S.gkey[g];
            const int nm = (key >> 24) & 7;
            unsigned int mm = key;
            float m = NEG_INF;
            for (int u = 0; u < nm; ++u) {
                const int bp = mm & 63; mm >>= 6;
                m = fmaxf(m, S.av[bp] * x1f[bp * (TT * RR) + t * RR + r]);
            }
            if (key >> 28) m = fmaxf(m, 0.f);
            acc += S.gcnt[g] * m;
        }
        // 4->4 matmul across the 4-lane r group
        float res = 0.f;
#pragma unroll
        for (int rout = 0; rout < RR; ++rout) {
            float p = acc * W_s[r * RR + rout];
            p += __shfl_xor_sync(0xFFFFFFFFu, p, 1);
            p += __shfl_xor_sync(0xFFFFFFFFu, p, 2);
            if (r == rout) res = p;
        }
        msum += fmaxf(res, 0.f);
    }

    // reduce msum over the 8 t-slots per warp (r preserved)
    msum += __shfl_xor_sync(0xFFFFFFFFu, msum, 4);
    msum += __shfl_xor_sync(0xFFFFFFFFu, msum, 8);
    msum += __shfl_xor_sync(0xFFFFFFFFu, msum, 16);
    if ((tid & 31) < 4) msm[tid >> 5][r] = msum;
    __syncthreads();
    if (tid < 4) {
        float p = 0.f;
#pragma unroll
        for (int wg = 0; wg < 16; ++wg) p += msm[wg][tid];
        msm[0][tid] = p * (1.0f / (float)TT);
    }
    __syncthreads();
    if (tid == 0) {
        float logit[NSTACK];
        float mx = NEG_INF;
#pragma unroll
        for (int n = 0; n < NSTACK; ++n) {
            float p = 0.f;
#pragma unroll
            for (int rr = 0; rr < RR; ++rr) p += msm[0][rr] * Wp[rr * NSTACK + n];
            logit[n] = p;
            mx = fmaxf(mx, p);
        }
        float se = 0.f;
#pragma unroll
        for (int n = 0; n < NSTACK; ++n) { logit[n] = expf(logit[n] - mx); se += logit[n]; }
        const float inv = 1.0f / se;
#pragma unroll
        for (int n = 0; n < NSTACK; ++n) outp[row * NSTACK + n] = logit[n] * inv;
    }
}

// =====================================================================
extern "C" void kernel_launch(void* const* d_in, const int* in_sizes, int n_in,
                              void* d_out, int out_size) {
    const float* x  = (const float*)d_in[0];  // [64,256,64]
    const float* W0 = (const float*)d_in[1];  // [64,4]
    const float* W1 = (const float*)d_in[2];  // [4,4]
    const float* Wp = (const float*)d_in[3];  // [4,8]
    float* out = (float*)d_out;               // [64,8]

    gram_partial_kernel<<<128, 256>>>(x);
    fused0_kernel<<<BB, 512>>>(x, W0);
    fused1_kernel<<<BB, 512>>>(W1, Wp, out);
}